// round 2
// baseline (speedup 1.0000x reference)
#include <cuda_runtime.h>

#define T_LEN 4995
#define BATCH 64
#define VOCAB 4096
#define EDIM  100
#define UDIM  64
#define G3    192   // 3*U gate width

// Precomputed (emb @ W1 + b1[0]) table: [VOCAB, 192]
__device__ float g_tab[VOCAB * G3];

__device__ __forceinline__ void ffma2(float2& acc, const float2 a, const float2 b) {
    asm("fma.rn.f32x2 %0, %1, %2, %0;"
        : "+l"(reinterpret_cast<unsigned long long&>(acc))
        : "l"(*reinterpret_cast<const unsigned long long*>(&a)),
          "l"(*reinterpret_cast<const unsigned long long*>(&b)));
}

__device__ __forceinline__ float sigf(float x) {
    return 1.0f / (1.0f + __expf(-x));
}
__device__ __forceinline__ float tanh_fast(float x) {
    float e = __expf(2.0f * x);
    return (e - 1.0f) * __fdividef(1.0f, e + 1.0f);
}

#define BAR192() asm volatile("bar.sync 0, 192;" ::: "memory")

// ---------------------------------------------------------------------------
// Kernel 1: g_tab[v][j] = sum_e emb[v][e] * W1[e][j] + b1[0][j]
// ---------------------------------------------------------------------------
__global__ void build_tab(const float* __restrict__ emb,
                          const float* __restrict__ W1,
                          const float* __restrict__ b1) {
    __shared__ float es[EDIM];
    const int v = blockIdx.x;
    const int j = threadIdx.x;
    for (int e = j; e < EDIM; e += G3) es[e] = emb[v * EDIM + e];
    __syncthreads();
    float s = b1[j];
#pragma unroll 4
    for (int e = 0; e < EDIM; e++) s += es[e] * __ldg(&W1[e * G3 + j]);
    g_tab[v * G3 + j] = s;
}

// ---------------------------------------------------------------------------
// Kernel 2: fused 2-layer GRU, one CTA per batch row, persistent over T.
//   threads   0..63 : layer-1 gates (U1 cols {j,j+64,j+128} in regs) -> h1new
//   threads  64..127: layer-2 recurrent dots (U2 cols) -> a2s
//   threads 128..191: xt prefetch (P1) + layer-2 input dots (W2 cols) + gates (P2)
// Per step: P1 | bar | P2 | bar   (2 barriers)
// ---------------------------------------------------------------------------
__global__ void __launch_bounds__(192, 1)
gru_fused(const int*   __restrict__ tokens,
          const float* __restrict__ U1w,
          const float* __restrict__ b1,
          const float* __restrict__ W2w,
          const float* __restrict__ U2w,
          const float* __restrict__ b2,
          const float* __restrict__ Wout,
          const float* __restrict__ bout,
          float*       __restrict__ out) {
    __shared__ int   toks[T_LEN];
    __shared__ __align__(16) float h1s[2][UDIM];   // double-buffered layer-1 state
    __shared__ __align__(16) float h2s[UDIM];
    __shared__ __align__(16) float a2s[G3];        // h2 @ U2 + b2[1]
    __shared__ __align__(16) float xtr[4][G3];     // xt ring, prefetch distance 3
    __shared__ __align__(16) float red[UDIM];

    const int tid = threadIdx.x;
    const int b   = blockIdx.x;

    if (tid < UDIM) { h1s[0][tid] = 0.0f; h2s[tid] = 0.0f; }
    for (int i = tid; i < T_LEN; i += G3)
        toks[i] = tokens[(long long)b * T_LEN + i];
    __syncthreads();
#pragma unroll
    for (int tp = 0; tp < 3; tp++) {
        const int tok = toks[tp];
        xtr[tp][tid] = g_tab[tok * G3 + tid];
    }
    __syncthreads();

    if (tid < 64) {
        // ---------------- Role A: layer-1 gate thread j ----------------
        const int j = tid;
        float2 w[3][32];
#pragma unroll
        for (int g = 0; g < 3; g++)
#pragma unroll
            for (int kk = 0; kk < 32; kk++)
                w[g][kk] = make_float2(U1w[(2 * kk) * G3 + g * 64 + j],
                                       U1w[(2 * kk + 1) * G3 + g * 64 + j]);
        const float bz = b1[G3 + j], br = b1[G3 + 64 + j], bh = b1[G3 + 128 + j];

        for (int t = 0; t < T_LEN; t++) {
            const int p = t & 1, s = t & 3;
            const float xz = xtr[s][j], xr = xtr[s][64 + j], xh = xtr[s][128 + j];
            const float2* hv = (const float2*)h1s[p];
            float2 a0 = {bz, 0.f}, a1 = {0.f, 0.f};
            float2 r0 = {br, 0.f}, r1 = {0.f, 0.f};
            float2 c0 = {bh, 0.f}, c1 = {0.f, 0.f};
#pragma unroll
            for (int kk = 0; kk < 32; kk += 2) {
                const float2 h0 = hv[kk], h1v = hv[kk + 1];
                ffma2(a0, h0, w[0][kk]); ffma2(a1, h1v, w[0][kk + 1]);
                ffma2(r0, h0, w[1][kk]); ffma2(r1, h1v, w[1][kk + 1]);
                ffma2(c0, h0, w[2][kk]); ffma2(c1, h1v, w[2][kk + 1]);
            }
            const float az = a0.x + a0.y + a1.x + a1.y;
            const float ar = r0.x + r0.y + r1.x + r1.y;
            const float ah = c0.x + c0.y + c1.x + c1.y;
            const float z  = sigf(xz + az);
            const float r  = sigf(xr + ar);
            const float hh = tanh_fast(xh + r * ah);
            const float hold = h1s[p][j];
            h1s[p ^ 1][j] = z * hold + (1.0f - z) * hh;
            BAR192();
            BAR192();
        }
    } else if (tid < 128) {
        // ---------------- Role B: layer-2 recurrent dots ----------------
        const int j = tid - 64;
        float2 w[3][32];
#pragma unroll
        for (int g = 0; g < 3; g++)
#pragma unroll
            for (int kk = 0; kk < 32; kk++)
                w[g][kk] = make_float2(U2w[(2 * kk) * G3 + g * 64 + j],
                                       U2w[(2 * kk + 1) * G3 + g * 64 + j]);
        const float bz = b2[G3 + j], br = b2[G3 + 64 + j], bh = b2[G3 + 128 + j];

        for (int t = 0; t < T_LEN; t++) {
            const float2* hv = (const float2*)h2s;
            float2 a0 = {bz, 0.f}, a1 = {0.f, 0.f};
            float2 r0 = {br, 0.f}, r1 = {0.f, 0.f};
            float2 c0 = {bh, 0.f}, c1 = {0.f, 0.f};
#pragma unroll
            for (int kk = 0; kk < 32; kk += 2) {
                const float2 h0 = hv[kk], h1v = hv[kk + 1];
                ffma2(a0, h0, w[0][kk]); ffma2(a1, h1v, w[0][kk + 1]);
                ffma2(r0, h0, w[1][kk]); ffma2(r1, h1v, w[1][kk + 1]);
                ffma2(c0, h0, w[2][kk]); ffma2(c1, h1v, w[2][kk + 1]);
            }
            a2s[j]        = a0.x + a0.y + a1.x + a1.y;
            a2s[64 + j]   = r0.x + r0.y + r1.x + r1.y;
            a2s[128 + j]  = c0.x + c0.y + c1.x + c1.y;
            BAR192();
            BAR192();
        }
    } else {
        // ---------------- Role C: xt prefetch + layer-2 input dots + gates ----
        const int j = tid - 128;
        float2 w[3][32];
#pragma unroll
        for (int g = 0; g < 3; g++)
#pragma unroll
            for (int kk = 0; kk < 32; kk++)
                w[g][kk] = make_float2(W2w[(2 * kk) * G3 + g * 64 + j],
                                       W2w[(2 * kk + 1) * G3 + g * 64 + j]);
        const float bz = b2[j], br = b2[64 + j], bh = b2[128 + j];

        for (int t = 0; t < T_LEN; t++) {
            // P1: prefetch xt for step t+3 (A/B are computing meanwhile)
            const int tp = t + 3;
            if (tp < T_LEN) {
                const int tok = toks[tp];
                const float* row = g_tab + tok * G3;
                xtr[tp & 3][j]       = row[j];
                xtr[tp & 3][64 + j]  = row[64 + j];
                xtr[tp & 3][128 + j] = row[128 + j];
            }
            BAR192();
            // P2: x2 = h1new @ W2 + b2[0]; then layer-2 gates
            const float2* hv = (const float2*)h1s[(t & 1) ^ 1];
            float2 a0 = {bz, 0.f}, a1 = {0.f, 0.f};
            float2 r0 = {br, 0.f}, r1 = {0.f, 0.f};
            float2 c0 = {bh, 0.f}, c1 = {0.f, 0.f};
#pragma unroll
            for (int kk = 0; kk < 32; kk += 2) {
                const float2 h0 = hv[kk], h1v = hv[kk + 1];
                ffma2(a0, h0, w[0][kk]); ffma2(a1, h1v, w[0][kk + 1]);
                ffma2(r0, h0, w[1][kk]); ffma2(r1, h1v, w[1][kk + 1]);
                ffma2(c0, h0, w[2][kk]); ffma2(c1, h1v, w[2][kk + 1]);
            }
            const float xz = a0.x + a0.y + a1.x + a1.y;
            const float xr = r0.x + r0.y + r1.x + r1.y;
            const float xh = c0.x + c0.y + c1.x + c1.y;
            const float z  = sigf(xz + a2s[j]);
            const float r  = sigf(xr + a2s[64 + j]);
            const float hh = tanh_fast(xh + r * a2s[128 + j]);
            h2s[j] = z * h2s[j] + (1.0f - z) * hh;
            BAR192();
        }
    }

    // ---------------- Epilogue: sigmoid(h2 @ Wout + bout) ----------------
    __syncthreads();
    if (tid < 64) red[tid] = h2s[tid] * Wout[tid];
    __syncthreads();
    if (tid == 0) {
        float s = bout[0];
#pragma unroll
        for (int k = 0; k < 64; k++) s += red[k];
        out[b] = 1.0f / (1.0f + __expf(-s));
    }
}

// ---------------------------------------------------------------------------
extern "C" void kernel_launch(void* const* d_in, const int* in_sizes, int n_in,
                              void* d_out, int out_size) {
    const int*   tokens = (const int*)  d_in[0];
    const float* emb    = (const float*)d_in[1];
    const float* W1     = (const float*)d_in[2];
    const float* U1     = (const float*)d_in[3];
    const float* b1     = (const float*)d_in[4];
    const float* W2     = (const float*)d_in[5];
    const float* U2     = (const float*)d_in[6];
    const float* b2     = (const float*)d_in[7];
    const float* Wout   = (const float*)d_in[8];
    const float* bout   = (const float*)d_in[9];

    build_tab<<<VOCAB, G3>>>(emb, W1, b1);
    gru_fused<<<BATCH, G3>>>(tokens, U1, b1, W2, U2, b2, Wout, bout,
                             (float*)d_out);
}